// round 7
// baseline (speedup 1.0000x reference)
#include <cuda_runtime.h>

// ---------------------------------------------------------------------------
// Edge_Labelling: out[e] = tanh(a[src[e]] + b[dst[e]] + c)
// a[n] = u . f_n, b[n] = v . f_n,
// u = W1^T (w2a + w2b), v = W1^T (w2b - w2a), c = 2*w2b.b1 + b2
// (exact algebraic collapse of the reference MLP)
//
// Two kernels: k_nodes fuses the weight fold (redundant per block, L2-deduped
// broadcast) with the per-node dual GEMV; k_edges gathers + tanh.
// ---------------------------------------------------------------------------

#define D 128
#define MAX_N (1 << 18)

__device__ float g_a[MAX_N];
__device__ float g_b[MAX_N];
__device__ float g_c;
__device__ int   g_is64;

// --- fused fold + per-node dual GEMV ----------------------------------------
__global__ __launch_bounds__(1024) void k_nodes(
        const float* __restrict__ feat,
        const float* __restrict__ W1, const float* __restrict__ b1,
        const float* __restrict__ W2, const float* __restrict__ b2,
        const long long* __restrict__ src, int N) {
    __shared__ float s_part_u[1024];
    __shared__ float s_part_v[1024];
    __shared__ __align__(16) float s_u[D];
    __shared__ __align__(16) float s_v[D];

    int tid = threadIdx.x;

    // ---- phase 1: fold weights into s_u, s_v (every block, L2-broadcast) ----
    {
        int d  = tid & (D - 1);
        int og = tid >> 7;            // 0..7 : 16-wide slice of o
        float au = 0.f, av = 0.f;
        #pragma unroll
        for (int k = 0; k < 16; ++k) {
            int o    = og * 16 + k;
            float w  = W1[o * D + d];  // coalesced across lanes
            float wa = W2[o];          // warp-uniform broadcast
            float wb = W2[D + o];
            au = fmaf(w, wa + wb, au);
            av = fmaf(w, wb - wa, av);
        }
        s_part_u[tid] = au;
        s_part_v[tid] = av;
    }

    // block 0 extras: scalar c and index-width detection (for k_edges)
    if (blockIdx.x == 0) {
        if (tid >= 256 && tid < 288) {
            int lane = tid - 256;
            float cc = 0.f;
            #pragma unroll
            for (int k = 0; k < 4; ++k) {
                int o = lane + k * 32;
                cc = fmaf(2.0f * b1[o], W2[D + o], cc);
            }
            #pragma unroll
            for (int off = 16; off > 0; off >>= 1)
                cc += __shfl_xor_sync(0xffffffffu, cc, off);
            if (lane == 0) g_c = cc + b2[0];
        }
        if (tid == 288) {
            // if stored int32, an int64 view pairs two random indices ->
            // almost surely out of [0, N)
            bool all_valid = true;
            #pragma unroll
            for (int i = 0; i < 16; ++i) {
                long long v = src[i];
                if (v < 0 || v >= (long long)N) all_valid = false;
            }
            g_is64 = all_valid ? 1 : 0;
        }
    }

    __syncthreads();
    if (tid < D) {
        float ta = 0.f, tv = 0.f;
        #pragma unroll
        for (int j = 0; j < 8; ++j) {
            ta += s_part_u[tid + j * D];
            tv += s_part_v[tid + j * D];
        }
        s_u[tid] = ta;
        s_v[tid] = tv;
    }
    __syncthreads();

    // ---- phase 2: grid-stride dual GEMV, 8 lanes per node -------------------
    const float4* uu = reinterpret_cast<const float4*>(s_u);
    const float4* vv = reinterpret_cast<const float4*>(s_v);
    int sub = tid & 7;
    int nodes_per_block = 1024 / 8;   // 128

    for (int node = blockIdx.x * nodes_per_block + (tid >> 3);
         node < N;
         node += gridDim.x * nodes_per_block) {
        const float4* row = reinterpret_cast<const float4*>(feat + (size_t)node * D);
        float au = 0.f, av = 0.f;
        #pragma unroll
        for (int k = 0; k < 4; ++k) {
            int c = sub + k * 8;      // 32 float4 chunks per row
            float4 x = row[c];
            float4 u = uu[c];
            float4 v = vv[c];
            au = fmaf(x.x, u.x, fmaf(x.y, u.y, fmaf(x.z, u.z, fmaf(x.w, u.w, au))));
            av = fmaf(x.x, v.x, fmaf(x.y, v.y, fmaf(x.z, v.z, fmaf(x.w, v.w, av))));
        }
        #pragma unroll
        for (int off = 4; off > 0; off >>= 1) {
            au += __shfl_xor_sync(0xffffffffu, au, off);
            av += __shfl_xor_sync(0xffffffffu, av, off);
        }
        if (sub == 0) {
            g_a[node] = au;
            g_b[node] = av;
        }
    }
}

// --- per-edge gather + tanh: 8 edges per thread ------------------------------
__global__ void k_edges(const void* __restrict__ src_raw, const void* __restrict__ dst_raw,
                        float* __restrict__ out, int E) {
    const float c = g_c;
    int i    = blockIdx.x * blockDim.x + threadIdx.x;
    int base = i * 8;
    if (base >= E) return;

    int si[8], di[8];

    if (g_is64) {
        if (base + 7 < E) {
            const longlong2* s2 = (const longlong2*)src_raw + (size_t)i * 4;
            const longlong2* d2 = (const longlong2*)dst_raw + (size_t)i * 4;
            #pragma unroll
            for (int j = 0; j < 4; ++j) {
                longlong2 s = s2[j], d = d2[j];
                si[2*j] = (int)s.x; si[2*j+1] = (int)s.y;
                di[2*j] = (int)d.x; di[2*j+1] = (int)d.y;
            }
        } else {
            const long long* s = (const long long*)src_raw;
            const long long* d = (const long long*)dst_raw;
            for (int e = base; e < E; ++e)
                out[e] = tanhf(__ldg(&g_a[(int)s[e]]) + __ldg(&g_b[(int)d[e]]) + c);
            return;
        }
    } else {
        if (base + 7 < E) {
            const int4* s4 = (const int4*)src_raw + (size_t)i * 2;
            const int4* d4 = (const int4*)dst_raw + (size_t)i * 2;
            #pragma unroll
            for (int j = 0; j < 2; ++j) {
                int4 s = s4[j], d = d4[j];
                si[4*j] = s.x; si[4*j+1] = s.y; si[4*j+2] = s.z; si[4*j+3] = s.w;
                di[4*j] = d.x; di[4*j+1] = d.y; di[4*j+2] = d.z; di[4*j+3] = d.w;
            }
        } else {
            const int* s = (const int*)src_raw;
            const int* d = (const int*)dst_raw;
            for (int e = base; e < E; ++e)
                out[e] = tanhf(__ldg(&g_a[s[e]]) + __ldg(&g_b[d[e]]) + c);
            return;
        }
    }

    // issue all 16 gathers before any tanh
    float a[8], b[8];
    #pragma unroll
    for (int j = 0; j < 8; ++j) a[j] = __ldg(&g_a[si[j]]);
    #pragma unroll
    for (int j = 0; j < 8; ++j) b[j] = __ldg(&g_b[di[j]]);

    float4 r0, r1;
    r0.x = tanhf(a[0] + b[0] + c);
    r0.y = tanhf(a[1] + b[1] + c);
    r0.z = tanhf(a[2] + b[2] + c);
    r0.w = tanhf(a[3] + b[3] + c);
    r1.x = tanhf(a[4] + b[4] + c);
    r1.y = tanhf(a[5] + b[5] + c);
    r1.z = tanhf(a[6] + b[6] + c);
    r1.w = tanhf(a[7] + b[7] + c);
    reinterpret_cast<float4*>(out)[i * 2]     = r0;
    reinterpret_cast<float4*>(out)[i * 2 + 1] = r1;
}

extern "C" void kernel_launch(void* const* d_in, const int* in_sizes, int n_in,
                              void* d_out, int out_size) {
    // inputs: features, src, dst, W1, b1, W2, b2
    const float* feat = (const float*)d_in[0];
    const void*  src  = d_in[1];
    const void*  dst  = d_in[2];
    const float* W1   = (const float*)d_in[3];
    const float* b1   = (const float*)d_in[4];
    const float* W2   = (const float*)d_in[5];
    const float* b2   = (const float*)d_in[6];
    float* out = (float*)d_out;

    const int N = in_sizes[0] / D;   // 50000
    const int E = in_sizes[1];       // 800000

    // fused fold + node GEMV: 296 blocks (2 per SM), grid-stride over nodes
    int nblocks = (N + 127) / 128;
    if (nblocks > 296) nblocks = 296;
    k_nodes<<<nblocks, 1024>>>(feat, W1, b1, W2, b2, (const long long*)src, N);

    // 8 edges per thread
    int nthreads = (E + 7) / 8;
    int eblocks  = (nthreads + 255) / 256;
    k_edges<<<eblocks, 256>>>(src, dst, out, E);
}

// round 8
// speedup vs baseline: 1.0034x; 1.0034x over previous
#include <cuda_runtime.h>

// ---------------------------------------------------------------------------
// Edge_Labelling: out[e] = tanh(a[src[e]] + b[dst[e]] + c)
// a[n] = u . f_n, b[n] = v . f_n,
// u = W1^T (w2a + w2b), v = W1^T (w2b - w2a), c = 2*w2b.b1 + b2
// (exact algebraic collapse of the reference MLP)
//
// Two kernels: k_nodes fuses the weight fold (redundant per block, L2-deduped
// broadcast) with the per-node dual GEMV; k_edges gathers + tanh.
// ---------------------------------------------------------------------------

#define D 128
#define MAX_N (1 << 18)

__device__ float g_a[MAX_N];
__device__ float g_b[MAX_N];
__device__ float g_c;
__device__ int   g_is64;

// --- fused fold + per-node dual GEMV ----------------------------------------
__global__ __launch_bounds__(1024) void k_nodes(
        const float* __restrict__ feat,
        const float* __restrict__ W1, const float* __restrict__ b1,
        const float* __restrict__ W2, const float* __restrict__ b2,
        const long long* __restrict__ src, int N) {
    __shared__ float s_part_u[1024];
    __shared__ float s_part_v[1024];
    __shared__ __align__(16) float s_u[D];
    __shared__ __align__(16) float s_v[D];

    int tid = threadIdx.x;

    // ---- phase 1: fold weights into s_u, s_v (every block, L2-broadcast) ----
    {
        int d  = tid & (D - 1);
        int og = tid >> 7;            // 0..7 : 16-wide slice of o
        float au = 0.f, av = 0.f;
        #pragma unroll
        for (int k = 0; k < 16; ++k) {
            int o    = og * 16 + k;
            float w  = W1[o * D + d];  // coalesced across lanes
            float wa = W2[o];          // warp-uniform broadcast
            float wb = W2[D + o];
            au = fmaf(w, wa + wb, au);
            av = fmaf(w, wb - wa, av);
        }
        s_part_u[tid] = au;
        s_part_v[tid] = av;
    }

    // block 0 extras: scalar c and index-width detection (for k_edges)
    if (blockIdx.x == 0) {
        if (tid >= 256 && tid < 288) {
            int lane = tid - 256;
            float cc = 0.f;
            #pragma unroll
            for (int k = 0; k < 4; ++k) {
                int o = lane + k * 32;
                cc = fmaf(2.0f * b1[o], W2[D + o], cc);
            }
            #pragma unroll
            for (int off = 16; off > 0; off >>= 1)
                cc += __shfl_xor_sync(0xffffffffu, cc, off);
            if (lane == 0) g_c = cc + b2[0];
        }
        if (tid == 288) {
            // if stored int32, an int64 view pairs two random indices ->
            // almost surely out of [0, N)
            bool all_valid = true;
            #pragma unroll
            for (int i = 0; i < 16; ++i) {
                long long v = src[i];
                if (v < 0 || v >= (long long)N) all_valid = false;
            }
            g_is64 = all_valid ? 1 : 0;
        }
    }

    __syncthreads();
    if (tid < D) {
        float ta = 0.f, tv = 0.f;
        #pragma unroll
        for (int j = 0; j < 8; ++j) {
            ta += s_part_u[tid + j * D];
            tv += s_part_v[tid + j * D];
        }
        s_u[tid] = ta;
        s_v[tid] = tv;
    }
    __syncthreads();

    // ---- phase 2: grid-stride dual GEMV, 8 lanes per node -------------------
    const float4* uu = reinterpret_cast<const float4*>(s_u);
    const float4* vv = reinterpret_cast<const float4*>(s_v);
    int sub = tid & 7;
    int nodes_per_block = 1024 / 8;   // 128

    for (int node = blockIdx.x * nodes_per_block + (tid >> 3);
         node < N;
         node += gridDim.x * nodes_per_block) {
        const float4* row = reinterpret_cast<const float4*>(feat + (size_t)node * D);
        float au = 0.f, av = 0.f;
        #pragma unroll
        for (int k = 0; k < 4; ++k) {
            int c = sub + k * 8;      // 32 float4 chunks per row
            float4 x = row[c];
            float4 u = uu[c];
            float4 v = vv[c];
            au = fmaf(x.x, u.x, fmaf(x.y, u.y, fmaf(x.z, u.z, fmaf(x.w, u.w, au))));
            av = fmaf(x.x, v.x, fmaf(x.y, v.y, fmaf(x.z, v.z, fmaf(x.w, v.w, av))));
        }
        #pragma unroll
        for (int off = 4; off > 0; off >>= 1) {
            au += __shfl_xor_sync(0xffffffffu, au, off);
            av += __shfl_xor_sync(0xffffffffu, av, off);
        }
        if (sub == 0) {
            g_a[node] = au;
            g_b[node] = av;
        }
    }
}

// --- per-edge gather + tanh: 8 edges per thread ------------------------------
__global__ void k_edges(const void* __restrict__ src_raw, const void* __restrict__ dst_raw,
                        float* __restrict__ out, int E) {
    const float c = g_c;
    int i    = blockIdx.x * blockDim.x + threadIdx.x;
    int base = i * 8;
    if (base >= E) return;

    int si[8], di[8];

    if (g_is64) {
        if (base + 7 < E) {
            const longlong2* s2 = (const longlong2*)src_raw + (size_t)i * 4;
            const longlong2* d2 = (const longlong2*)dst_raw + (size_t)i * 4;
            #pragma unroll
            for (int j = 0; j < 4; ++j) {
                longlong2 s = s2[j], d = d2[j];
                si[2*j] = (int)s.x; si[2*j+1] = (int)s.y;
                di[2*j] = (int)d.x; di[2*j+1] = (int)d.y;
            }
        } else {
            const long long* s = (const long long*)src_raw;
            const long long* d = (const long long*)dst_raw;
            for (int e = base; e < E; ++e)
                out[e] = tanhf(__ldg(&g_a[(int)s[e]]) + __ldg(&g_b[(int)d[e]]) + c);
            return;
        }
    } else {
        if (base + 7 < E) {
            const int4* s4 = (const int4*)src_raw + (size_t)i * 2;
            const int4* d4 = (const int4*)dst_raw + (size_t)i * 2;
            #pragma unroll
            for (int j = 0; j < 2; ++j) {
                int4 s = s4[j], d = d4[j];
                si[4*j] = s.x; si[4*j+1] = s.y; si[4*j+2] = s.z; si[4*j+3] = s.w;
                di[4*j] = d.x; di[4*j+1] = d.y; di[4*j+2] = d.z; di[4*j+3] = d.w;
            }
        } else {
            const int* s = (const int*)src_raw;
            const int* d = (const int*)dst_raw;
            for (int e = base; e < E; ++e)
                out[e] = tanhf(__ldg(&g_a[s[e]]) + __ldg(&g_b[d[e]]) + c);
            return;
        }
    }

    // issue all 16 gathers before any tanh
    float a[8], b[8];
    #pragma unroll
    for (int j = 0; j < 8; ++j) a[j] = __ldg(&g_a[si[j]]);
    #pragma unroll
    for (int j = 0; j < 8; ++j) b[j] = __ldg(&g_b[di[j]]);

    float4 r0, r1;
    r0.x = tanhf(a[0] + b[0] + c);
    r0.y = tanhf(a[1] + b[1] + c);
    r0.z = tanhf(a[2] + b[2] + c);
    r0.w = tanhf(a[3] + b[3] + c);
    r1.x = tanhf(a[4] + b[4] + c);
    r1.y = tanhf(a[5] + b[5] + c);
    r1.z = tanhf(a[6] + b[6] + c);
    r1.w = tanhf(a[7] + b[7] + c);
    reinterpret_cast<float4*>(out)[i * 2]     = r0;
    reinterpret_cast<float4*>(out)[i * 2 + 1] = r1;
}

extern "C" void kernel_launch(void* const* d_in, const int* in_sizes, int n_in,
                              void* d_out, int out_size) {
    // inputs: features, src, dst, W1, b1, W2, b2
    const float* feat = (const float*)d_in[0];
    const void*  src  = d_in[1];
    const void*  dst  = d_in[2];
    const float* W1   = (const float*)d_in[3];
    const float* b1   = (const float*)d_in[4];
    const float* W2   = (const float*)d_in[5];
    const float* b2   = (const float*)d_in[6];
    float* out = (float*)d_out;

    const int N = in_sizes[0] / D;   // 50000
    const int E = in_sizes[1];       // 800000

    // fused fold + node GEMV: 296 blocks (2 per SM), grid-stride over nodes
    int nblocks = (N + 127) / 128;
    if (nblocks > 296) nblocks = 296;
    k_nodes<<<nblocks, 1024>>>(feat, W1, b1, W2, b2, (const long long*)src, N);

    // 8 edges per thread
    int nthreads = (E + 7) / 8;
    int eblocks  = (nthreads + 255) / 256;
    k_edges<<<eblocks, 256>>>(src, dst, out, E);
}